// round 1
// baseline (speedup 1.0000x reference)
#include <cuda_runtime.h>
#include <math.h>

#define BATCH 8
#define NINST 8192
#define DIM   512
#define HID   64
#define TOPK_K 2457
#define ROWCHUNKS 8
#define ROWS_PER_CHUNK (NINST / ROWCHUNKS)

// scratch (device globals; no allocation allowed)
__device__ float    g_part[ROWCHUNKS * BATCH * DIM];  // partial weighted sums
__device__ float    g_h1[BATCH * DIM];                // hidden of projection MLP
__device__ unsigned g_thr[BATCH];                     // k-th largest weight (bits)
__device__ int      g_cut[BATCH];                     // tie cutoff index

__device__ __forceinline__ float gelu_f(float v) {
    // jax.nn.gelu approximate=True (tanh form)
    float u = 0.7978845608028654f * (v + 0.044715f * v * v * v);
    return 0.5f * v * (1.0f + tanhf(u));
}

// ---------------------------------------------------------------------------
// Kernel 1: fused attention-score MLP.
// weights[b,n] = sigmoid( gelu(x[b,n,:] @ aW1 + ab1) @ aW2 + ab2 )
// Register-tiled SGEMM: block = 128 rows x 64 hidden, K chunked by 16,
// 128 threads, 8x8 microtile per thread.
// ---------------------------------------------------------------------------
__global__ __launch_bounds__(128) void attn_kernel(
    const float* __restrict__ x,
    const float* __restrict__ aW1,
    const float* __restrict__ ab1,
    const float* __restrict__ aW2,
    const float* __restrict__ ab2,
    float* __restrict__ wout)
{
    __shared__ float As[16][132];   // [k][row] transposed, padded
    __shared__ float Bs[16][64];    // [k][hid]

    const int tid = threadIdx.x;
    const int tx = tid & 7;        // hidden group (8 cols each)
    const int ty = tid >> 3;       // row group (8 rows each), 0..15
    const long rowBase = (long)blockIdx.x * 128;
    const float* xb = x + rowBase * DIM;

    float acc[8][8];
    #pragma unroll
    for (int i = 0; i < 8; i++)
        #pragma unroll
        for (int j = 0; j < 8; j++) acc[i][j] = 0.f;

    const int kr = tid >> 3;            // 0..15 (W1 row within chunk)
    const int jc = (tid & 7) * 8;       // W1 col start

    for (int kk = 0; kk < DIM; kk += 16) {
        // load x tile: thread loads 16 contiguous floats of its own row
        const float4* src = reinterpret_cast<const float4*>(xb + (long)tid * DIM + kk);
        float4 v0 = src[0], v1 = src[1], v2 = src[2], v3 = src[3];
        // load W1 tile: 16 rows x 64 cols
        const float4* wsrc = reinterpret_cast<const float4*>(aW1 + (long)(kk + kr) * HID + jc);
        float4 w0 = wsrc[0], w1 = wsrc[1];

        As[ 0][tid] = v0.x; As[ 1][tid] = v0.y; As[ 2][tid] = v0.z; As[ 3][tid] = v0.w;
        As[ 4][tid] = v1.x; As[ 5][tid] = v1.y; As[ 6][tid] = v1.z; As[ 7][tid] = v1.w;
        As[ 8][tid] = v2.x; As[ 9][tid] = v2.y; As[10][tid] = v2.z; As[11][tid] = v2.w;
        As[12][tid] = v3.x; As[13][tid] = v3.y; As[14][tid] = v3.z; As[15][tid] = v3.w;
        *reinterpret_cast<float4*>(&Bs[kr][jc])     = w0;
        *reinterpret_cast<float4*>(&Bs[kr][jc + 4]) = w1;
        __syncthreads();

        #pragma unroll
        for (int k = 0; k < 16; k++) {
            float4 a0 = *reinterpret_cast<const float4*>(&As[k][ty * 8]);
            float4 a1 = *reinterpret_cast<const float4*>(&As[k][ty * 8 + 4]);
            float4 b0 = *reinterpret_cast<const float4*>(&Bs[k][tx * 8]);
            float4 b1 = *reinterpret_cast<const float4*>(&Bs[k][tx * 8 + 4]);
            float a[8] = {a0.x, a0.y, a0.z, a0.w, a1.x, a1.y, a1.z, a1.w};
            float b[8] = {b0.x, b0.y, b0.z, b0.w, b1.x, b1.y, b1.z, b1.w};
            #pragma unroll
            for (int i = 0; i < 8; i++)
                #pragma unroll
                for (int j = 0; j < 8; j++)
                    acc[i][j] += a[i] * b[j];
        }
        __syncthreads();
    }

    // epilogue: gelu + dot with aW2 + sigmoid
    float b1r[8], w2r[8];
    #pragma unroll
    for (int j = 0; j < 8; j++) {
        b1r[j] = ab1[tx * 8 + j];
        w2r[j] = aW2[tx * 8 + j];
    }
    float bias2 = ab2[0];

    float res[8];
    #pragma unroll
    for (int i = 0; i < 8; i++) {
        float p = 0.f;
        #pragma unroll
        for (int j = 0; j < 8; j++)
            p += gelu_f(acc[i][j] + b1r[j]) * w2r[j];
        // reduce across the 8 lanes sharing this row (consecutive lanes, width 8)
        p += __shfl_down_sync(0xffffffffu, p, 4, 8);
        p += __shfl_down_sync(0xffffffffu, p, 2, 8);
        p += __shfl_down_sync(0xffffffffu, p, 1, 8);
        res[i] = p;
    }
    if (tx == 0) {
        #pragma unroll
        for (int i = 0; i < 8; i++) {
            float s = res[i] + bias2;
            float w = 1.0f / (1.0f + expf(-s));
            wout[rowBase + ty * 8 + i] = w;
        }
    }
}

// ---------------------------------------------------------------------------
// Kernel 2: per-batch radix-select of the TOPK-th largest weight + exact tie
// cutoff by lowest index (matches jax.lax.top_k tie semantics).
// One block per batch, 256 threads.
// ---------------------------------------------------------------------------
__global__ __launch_bounds__(256) void select_kernel(const float* __restrict__ w)
{
    __shared__ unsigned sv[NINST];
    __shared__ int hist[256];
    __shared__ int tcnt[256];
    __shared__ unsigned s_prefix;
    __shared__ int s_k;

    const int b = blockIdx.x;
    const int tid = threadIdx.x;
    const float* wb = w + b * NINST;

    for (int i = tid; i < NINST; i += 256)
        sv[i] = __float_as_uint(wb[i]);   // all weights > 0 -> uint order == float order
    if (tid == 0) { s_prefix = 0u; s_k = TOPK_K; }
    __syncthreads();

    for (int r = 0; r < 4; r++) {
        hist[tid] = 0;
        __syncthreads();
        const unsigned pref = s_prefix;
        const int sh = 24 - 8 * r;
        for (int i = tid; i < NINST; i += 256) {
            unsigned v = sv[i];
            bool ok = (r == 0) || ((v >> (sh + 8)) == pref);
            if (ok) atomicAdd(&hist[(v >> sh) & 255], 1);
        }
        __syncthreads();
        if (tid == 0) {
            int k = s_k, cum = 0, bsel = 0;
            for (int bb = 255; bb >= 0; --bb) {
                cum += hist[bb];
                if (cum >= k) { bsel = bb; s_k = k - (cum - hist[bb]); break; }
            }
            s_prefix = (pref << 8) | (unsigned)bsel;
        }
        __syncthreads();
    }

    const unsigned thrv = s_prefix;   // exact bits of the k-th largest weight
    const int m = s_k;                // number of ties to include (>= 1)

    // find index of the m-th equal element (in ascending index order)
    const int base = tid * (NINST / 256);
    int local = 0;
    #pragma unroll 4
    for (int i = 0; i < NINST / 256; i++)
        if (sv[base + i] == thrv) local++;
    tcnt[tid] = local;
    __syncthreads();
    if (tid == 0) {
        int s = 0;
        for (int t = 0; t < 256; t++) { int c = tcnt[t]; tcnt[t] = s; s += c; }
    }
    __syncthreads();
    int rank = tcnt[tid];
    for (int i = 0; i < NINST / 256; i++) {
        if (sv[base + i] == thrv) {
            rank++;
            if (rank == m) g_cut[b] = base + i;
        }
    }
    if (tid == 0) g_thr[b] = thrv;
}

// ---------------------------------------------------------------------------
// Kernel 3: weighted gather-sum of selected rows into partial buffers
// (deterministic: fixed row-chunk partials, summed later in fixed order).
// grid = (DIM/128, ROWCHUNKS, BATCH), block = 128.
// ---------------------------------------------------------------------------
__global__ __launch_bounds__(128) void gather_kernel(
    const float* __restrict__ x, const float* __restrict__ w)
{
    const int b  = blockIdx.z;
    const int rc = blockIdx.y;
    const int d  = blockIdx.x * 128 + threadIdx.x;
    const int r0 = rc * ROWS_PER_CHUNK;

    const unsigned tv = g_thr[b];
    const int cu = g_cut[b];
    const float* wb = w + b * NINST + r0;
    const float* xb = x + ((long)b * NINST + r0) * DIM + d;

    float acc = 0.f;
    #pragma unroll 4
    for (int i = 0; i < ROWS_PER_CHUNK; i++) {
        float wi = wb[i];
        unsigned v = __float_as_uint(wi);
        if (v > tv || (v == tv && (r0 + i) <= cu))
            acc += wi * xb[(long)i * DIM];
    }
    g_part[(rc * BATCH + b) * DIM + d] = acc;
}

// ---------------------------------------------------------------------------
// Kernel 4: h1 = gelu(emb @ pW1 + pb1), emb = (sum of partials) / TOPK
// grid = (DIM/128, BATCH), block = 128.
// ---------------------------------------------------------------------------
__global__ __launch_bounds__(128) void mlp1_kernel(
    const float* __restrict__ W, const float* __restrict__ bias)
{
    __shared__ float semb[DIM];
    const int b = blockIdx.y;
    const int j = blockIdx.x * 128 + threadIdx.x;

    for (int d = threadIdx.x; d < DIM; d += 128) {
        float s = 0.f;
        #pragma unroll
        for (int rc = 0; rc < ROWCHUNKS; rc++)
            s += g_part[(rc * BATCH + b) * DIM + d];
        semb[d] = s * (1.0f / (float)TOPK_K);
    }
    __syncthreads();

    float acc = 0.f;
    #pragma unroll 8
    for (int d = 0; d < DIM; d++)
        acc += semb[d] * W[d * DIM + j];
    g_h1[b * DIM + j] = gelu_f(acc + bias[j]);
}

// ---------------------------------------------------------------------------
// Kernel 5: projection = h1 @ pW2 + pb2  -> d_out[0 .. B*DIM)
// ---------------------------------------------------------------------------
__global__ __launch_bounds__(128) void mlp2_kernel(
    const float* __restrict__ W, const float* __restrict__ bias,
    float* __restrict__ out)
{
    __shared__ float sh[DIM];
    const int b = blockIdx.y;
    const int j = blockIdx.x * 128 + threadIdx.x;

    for (int d = threadIdx.x; d < DIM; d += 128)
        sh[d] = g_h1[b * DIM + d];
    __syncthreads();

    float acc = 0.f;
    #pragma unroll 8
    for (int d = 0; d < DIM; d++)
        acc += sh[d] * W[d * DIM + j];
    out[b * DIM + j] = acc + bias[j];
}

// ---------------------------------------------------------------------------
extern "C" void kernel_launch(void* const* d_in, const int* in_sizes, int n_in,
                              void* d_out, int out_size)
{
    const float* x   = (const float*)d_in[0];
    const float* aW1 = (const float*)d_in[1];
    const float* ab1 = (const float*)d_in[2];
    const float* aW2 = (const float*)d_in[3];
    const float* ab2 = (const float*)d_in[4];
    const float* pW1 = (const float*)d_in[5];
    const float* pb1 = (const float*)d_in[6];
    const float* pW2 = (const float*)d_in[7];
    const float* pb2 = (const float*)d_in[8];

    float* out = (float*)d_out;
    float* proj    = out;                 // [B, DIM]
    float* weights = out + BATCH * DIM;   // [B, NINST]

    attn_kernel<<<(BATCH * NINST) / 128, 128>>>(x, aW1, ab1, aW2, ab2, weights);
    select_kernel<<<BATCH, 256>>>(weights);
    gather_kernel<<<dim3(DIM / 128, ROWCHUNKS, BATCH), 128>>>(x, weights);
    mlp1_kernel<<<dim3(DIM / 128, BATCH), 128>>>(pW1, pb1);
    mlp2_kernel<<<dim3(DIM / 128, BATCH), 128>>>(pW2, pb2, proj);
}

// round 2
// speedup vs baseline: 1.4845x; 1.4845x over previous
#include <cuda_runtime.h>
#include <math.h>

#define BATCH 8
#define NINST 8192
#define DIM   512
#define HID   64
#define TOPK_K 2457

// gather chunking
#define GCHUNKS 32
#define GROWS   (NINST / GCHUNKS)   // 256

// mlp split-K
#define KCHUNKS 8
#define KLEN    (DIM / KCHUNKS)     // 64

// scratch (device globals; no allocation allowed)
__device__ float    g_part[GCHUNKS * BATCH * DIM];   // gather partials (512KB)
__device__ float    g_emb[BATCH * DIM];              // pooled embedding
__device__ float    g_p1[KCHUNKS * BATCH * DIM];     // mlp1 partials
__device__ float    g_h1[BATCH * DIM];               // mlp1 output
__device__ float    g_p2[KCHUNKS * BATCH * DIM];     // mlp2 partials
__device__ unsigned g_thr[BATCH];                    // k-th largest weight (bits)
__device__ int      g_cut[BATCH];                    // tie cutoff index

__device__ __forceinline__ float gelu_f(float v) {
    float u = 0.7978845608028654f * (v + 0.044715f * v * v * v);
    return 0.5f * v * (1.0f + tanhf(u));
}

__device__ __forceinline__ void fma2(unsigned long long& d,
                                     unsigned long long a,
                                     unsigned long long b) {
    asm("fma.rn.f32x2 %0, %1, %2, %0;" : "+l"(d) : "l"(a), "l"(b));
}
__device__ __forceinline__ unsigned long long dup2(float a) {
    unsigned long long d;
    asm("mov.b64 %0, {%1, %1};" : "=l"(d) : "f"(a));
    return d;
}
__device__ __forceinline__ void unpack2(unsigned long long v, float& lo, float& hi) {
    asm("mov.b64 {%0, %1}, %2;" : "=f"(lo), "=f"(hi) : "l"(v));
}

// ---------------------------------------------------------------------------
// Kernel 1: fused attention-score MLP with packed f32x2 FMA.
// 128 rows x 64 hidden per block, K chunked by 16, 128 threads, 8x8 microtile.
// ---------------------------------------------------------------------------
__global__ __launch_bounds__(128) void attn_kernel(
    const float* __restrict__ x,
    const float* __restrict__ aW1,
    const float* __restrict__ ab1,
    const float* __restrict__ aW2,
    const float* __restrict__ ab2,
    float* __restrict__ wout)
{
    __shared__ float As[16][132];   // [k][row] transposed, padded
    __shared__ float Bs[16][64];    // [k][hid]

    const int tid = threadIdx.x;
    const int tx = tid & 7;        // hidden group (8 cols)
    const int ty = tid >> 3;       // row group (8 rows)
    const long rowBase = (long)blockIdx.x * 128;
    const float* xb = x + rowBase * DIM;

    unsigned long long acc2[8][4];
    #pragma unroll
    for (int i = 0; i < 8; i++)
        #pragma unroll
        for (int j = 0; j < 4; j++) acc2[i][j] = 0ull;

    const int kr = tid >> 3;
    const int jc = (tid & 7) * 8;

    for (int kk = 0; kk < DIM; kk += 16) {
        const float4* src = reinterpret_cast<const float4*>(xb + (long)tid * DIM + kk);
        float4 v0 = src[0], v1 = src[1], v2 = src[2], v3 = src[3];
        const float4* wsrc = reinterpret_cast<const float4*>(aW1 + (long)(kk + kr) * HID + jc);
        float4 w0 = wsrc[0], w1 = wsrc[1];

        As[ 0][tid] = v0.x; As[ 1][tid] = v0.y; As[ 2][tid] = v0.z; As[ 3][tid] = v0.w;
        As[ 4][tid] = v1.x; As[ 5][tid] = v1.y; As[ 6][tid] = v1.z; As[ 7][tid] = v1.w;
        As[ 8][tid] = v2.x; As[ 9][tid] = v2.y; As[10][tid] = v2.z; As[11][tid] = v2.w;
        As[12][tid] = v3.x; As[13][tid] = v3.y; As[14][tid] = v3.z; As[15][tid] = v3.w;
        *reinterpret_cast<float4*>(&Bs[kr][jc])     = w0;
        *reinterpret_cast<float4*>(&Bs[kr][jc + 4]) = w1;
        __syncthreads();

        #pragma unroll
        for (int k = 0; k < 16; k++) {
            const unsigned long long* bp =
                reinterpret_cast<const unsigned long long*>(&Bs[k][tx * 8]);
            unsigned long long b0 = bp[0], b1 = bp[1], b2 = bp[2], b3 = bp[3];
            float4 a0 = *reinterpret_cast<const float4*>(&As[k][ty * 8]);
            float4 a1 = *reinterpret_cast<const float4*>(&As[k][ty * 8 + 4]);
            float a[8] = {a0.x, a0.y, a0.z, a0.w, a1.x, a1.y, a1.z, a1.w};
            #pragma unroll
            for (int i = 0; i < 8; i++) {
                unsigned long long ad = dup2(a[i]);
                fma2(acc2[i][0], ad, b0);
                fma2(acc2[i][1], ad, b1);
                fma2(acc2[i][2], ad, b2);
                fma2(acc2[i][3], ad, b3);
            }
        }
        __syncthreads();
    }

    // epilogue: gelu + dot with aW2 + sigmoid
    float b1r[8], w2r[8];
    #pragma unroll
    for (int j = 0; j < 8; j++) {
        b1r[j] = ab1[tx * 8 + j];
        w2r[j] = aW2[tx * 8 + j];
    }
    float bias2 = ab2[0];

    float res[8];
    #pragma unroll
    for (int i = 0; i < 8; i++) {
        float p = 0.f;
        #pragma unroll
        for (int jp = 0; jp < 4; jp++) {
            float lo, hi;
            unpack2(acc2[i][jp], lo, hi);
            p += gelu_f(lo + b1r[2 * jp])     * w2r[2 * jp];
            p += gelu_f(hi + b1r[2 * jp + 1]) * w2r[2 * jp + 1];
        }
        p += __shfl_down_sync(0xffffffffu, p, 4, 8);
        p += __shfl_down_sync(0xffffffffu, p, 2, 8);
        p += __shfl_down_sync(0xffffffffu, p, 1, 8);
        res[i] = p;
    }
    if (tx == 0) {
        #pragma unroll
        for (int i = 0; i < 8; i++) {
            float s = res[i] + bias2;
            wout[rowBase + ty * 8 + i] = 1.0f / (1.0f + expf(-s));
        }
    }
}

// ---------------------------------------------------------------------------
// Kernel 2: per-batch radix-select (4x8-bit) + exact tie cutoff by lowest idx.
// One block per batch, 256 threads; per-warp histograms to cut atomics.
// ---------------------------------------------------------------------------
__global__ __launch_bounds__(256) void select_kernel(const float* __restrict__ w)
{
    __shared__ unsigned sv[NINST];
    __shared__ int hist[8][256];
    __shared__ int tcnt[256];
    __shared__ unsigned s_prefix;
    __shared__ int s_k;

    const int b = blockIdx.x;
    const int tid = threadIdx.x;
    const int wid = tid >> 5;
    const float* wb = w + b * NINST;

    for (int i = tid; i < NINST; i += 256)
        sv[i] = __float_as_uint(wb[i]);   // weights > 0 -> uint order == float order
    if (tid == 0) { s_prefix = 0u; s_k = TOPK_K; }
    __syncthreads();

    for (int r = 0; r < 4; r++) {
        #pragma unroll
        for (int h = 0; h < 8; h++) hist[h][tid] = 0;
        __syncthreads();
        const unsigned pref = s_prefix;
        const int sh = 24 - 8 * r;
        for (int i = tid; i < NINST; i += 256) {
            unsigned v = sv[i];
            bool ok = (r == 0) || ((v >> (sh + 8)) == pref);
            if (ok) atomicAdd(&hist[wid][(v >> sh) & 255], 1);
        }
        __syncthreads();
        // fold per-warp hists into hist[0]
        int s = hist[0][tid];
        #pragma unroll
        for (int h = 1; h < 8; h++) s += hist[h][tid];
        hist[0][tid] = s;
        __syncthreads();
        if (tid == 0) {
            int k = s_k, cum = 0, bsel = 0;
            for (int bb = 255; bb >= 0; --bb) {
                cum += hist[0][bb];
                if (cum >= k) { bsel = bb; s_k = k - (cum - hist[0][bb]); break; }
            }
            s_prefix = (pref << 8) | (unsigned)bsel;
        }
        __syncthreads();
    }

    const unsigned thrv = s_prefix;
    const int m = s_k;               // #ties to include (>= 1)

    const int base = tid * (NINST / 256);
    int local = 0;
    #pragma unroll 4
    for (int i = 0; i < NINST / 256; i++)
        if (sv[base + i] == thrv) local++;
    tcnt[tid] = local;
    __syncthreads();
    if (tid == 0) {
        int s = 0;
        for (int t = 0; t < 256; t++) { int c = tcnt[t]; tcnt[t] = s; s += c; }
    }
    __syncthreads();
    int rank = tcnt[tid];
    for (int i = 0; i < NINST / 256; i++) {
        if (sv[base + i] == thrv) {
            rank++;
            if (rank == m) g_cut[b] = base + i;
        }
    }
    if (tid == 0) g_thr[b] = thrv;
}

// ---------------------------------------------------------------------------
// Kernel 3: weighted gather-sum. One block per (batch, 256-row chunk);
// 128 threads x float4 = full 512-dim row per block. Deterministic partials.
// grid = (GCHUNKS, BATCH), block = 128.
// ---------------------------------------------------------------------------
__global__ __launch_bounds__(128) void gather_kernel(
    const float* __restrict__ x, const float* __restrict__ w)
{
    const int b  = blockIdx.y;
    const int rc = blockIdx.x;
    const int r0 = rc * GROWS;
    const int d4 = threadIdx.x * 4;

    const unsigned tv = g_thr[b];
    const int cu = g_cut[b];
    const float* wb = w + b * NINST + r0;
    const float* xb = x + ((long)b * NINST + r0) * DIM + d4;

    float4 acc = make_float4(0.f, 0.f, 0.f, 0.f);
    float wnext = wb[0];
    #pragma unroll 4
    for (int i = 0; i < GROWS; i++) {
        float wi = wnext;
        if (i + 1 < GROWS) wnext = wb[i + 1];
        unsigned v = __float_as_uint(wi);
        if (v > tv || (v == tv && (r0 + i) <= cu)) {
            float4 xv = *reinterpret_cast<const float4*>(xb + (long)i * DIM);
            acc.x += wi * xv.x; acc.y += wi * xv.y;
            acc.z += wi * xv.z; acc.w += wi * xv.w;
        }
    }
    *reinterpret_cast<float4*>(&g_part[(rc * BATCH + b) * DIM + d4]) = acc;
}

// ---------------------------------------------------------------------------
// Kernel 4: emb[b,d] = (sum of 32 partials) / TOPK.  grid=BATCH, block=512.
// ---------------------------------------------------------------------------
__global__ __launch_bounds__(512) void emb_kernel()
{
    const int b = blockIdx.x;
    const int d = threadIdx.x;
    float s = 0.f;
    #pragma unroll
    for (int rc = 0; rc < GCHUNKS; rc++)
        s += g_part[(rc * BATCH + b) * DIM + d];
    g_emb[b * DIM + d] = s * (1.0f / (float)TOPK_K);
}

// ---------------------------------------------------------------------------
// Kernel 5/7: split-K GEMM partials: part[kc][b][j] = sum_{d in kc} in[b,d]*W[d,j]
// grid = (DIM/128, KCHUNKS), block = 128; 8 batch-accumulators per thread.
// ---------------------------------------------------------------------------
__global__ __launch_bounds__(128) void mlp_part_kernel(
    const float* __restrict__ in,   // [B, DIM]
    const float* __restrict__ W,    // [DIM, DIM]
    float* __restrict__ part)       // [KCHUNKS, B, DIM]
{
    __shared__ float s_in[BATCH][KLEN];
    const int kc = blockIdx.y;
    const int j  = blockIdx.x * 128 + threadIdx.x;

    #pragma unroll
    for (int it = 0; it < (BATCH * KLEN) / 128; it++) {
        int i = it * 128 + threadIdx.x;
        int bb = i / KLEN, dd = i % KLEN;
        s_in[bb][dd] = in[bb * DIM + kc * KLEN + dd];
    }
    __syncthreads();

    float acc[BATCH];
    #pragma unroll
    for (int bb = 0; bb < BATCH; bb++) acc[bb] = 0.f;

    #pragma unroll 4
    for (int dd = 0; dd < KLEN; dd++) {
        float wv = W[(long)(kc * KLEN + dd) * DIM + j];
        #pragma unroll
        for (int bb = 0; bb < BATCH; bb++)
            acc[bb] += s_in[bb][dd] * wv;
    }
    #pragma unroll
    for (int bb = 0; bb < BATCH; bb++)
        part[(kc * BATCH + bb) * DIM + j] = acc[bb];
}

// ---------------------------------------------------------------------------
// Kernel 6: reduce mlp1 partials + bias + gelu -> g_h1. grid=BATCH, block=512.
// ---------------------------------------------------------------------------
__global__ __launch_bounds__(512) void mlp1_reduce_kernel(const float* __restrict__ bias)
{
    const int b = blockIdx.x;
    const int j = threadIdx.x;
    float s = 0.f;
    #pragma unroll
    for (int kc = 0; kc < KCHUNKS; kc++)
        s += g_p1[(kc * BATCH + b) * DIM + j];
    g_h1[b * DIM + j] = gelu_f(s + bias[j]);
}

// ---------------------------------------------------------------------------
// Kernel 8: reduce mlp2 partials + bias -> out. grid=BATCH, block=512.
// ---------------------------------------------------------------------------
__global__ __launch_bounds__(512) void mlp2_reduce_kernel(
    const float* __restrict__ bias, float* __restrict__ out)
{
    const int b = blockIdx.x;
    const int j = threadIdx.x;
    float s = 0.f;
    #pragma unroll
    for (int kc = 0; kc < KCHUNKS; kc++)
        s += g_p2[(kc * BATCH + b) * DIM + j];
    out[b * DIM + j] = s + bias[j];
}

// ---------------------------------------------------------------------------
extern "C" void kernel_launch(void* const* d_in, const int* in_sizes, int n_in,
                              void* d_out, int out_size)
{
    const float* x   = (const float*)d_in[0];
    const float* aW1 = (const float*)d_in[1];
    const float* ab1 = (const float*)d_in[2];
    const float* aW2 = (const float*)d_in[3];
    const float* ab2 = (const float*)d_in[4];
    const float* pW1 = (const float*)d_in[5];
    const float* pb1 = (const float*)d_in[6];
    const float* pW2 = (const float*)d_in[7];
    const float* pb2 = (const float*)d_in[8];

    float* out = (float*)d_out;
    float* proj    = out;                 // [B, DIM]
    float* weights = out + BATCH * DIM;   // [B, NINST]

    float* d_p1; cudaGetSymbolAddress((void**)&d_p1, g_p1);
    float* d_p2; cudaGetSymbolAddress((void**)&d_p2, g_p2);
    float* d_emb; cudaGetSymbolAddress((void**)&d_emb, g_emb);
    float* d_h1; cudaGetSymbolAddress((void**)&d_h1, g_h1);

    attn_kernel<<<(BATCH * NINST) / 128, 128>>>(x, aW1, ab1, aW2, ab2, weights);
    select_kernel<<<BATCH, 256>>>(weights);
    gather_kernel<<<dim3(GCHUNKS, BATCH), 128>>>(x, weights);
    emb_kernel<<<BATCH, 512>>>();
    mlp_part_kernel<<<dim3(DIM / 128, KCHUNKS), 128>>>(d_emb, pW1, d_p1);
    mlp1_reduce_kernel<<<BATCH, 512>>>(pb1);
    mlp_part_kernel<<<dim3(DIM / 128, KCHUNKS), 128>>>(d_h1, pW2, d_p2);
    mlp2_reduce_kernel<<<BATCH, 512>>>(pb2, proj);
}